// round 15
// baseline (speedup 1.0000x reference)
#include <cuda_runtime.h>
#include <math_constants.h>
#include <cstdint>

#define N_PTS 16384
#define C_DIM 64
#define K_NN  16
#define BQ    128               // points per block-tile
#define NBLK  (N_PTS / BQ)      // 128
#define NPAIR (NBLK * (NBLK + 1) / 2)   // 8256
#define NT    512
#define STRX  66                // x tile row stride (33 u64 -> conflict-free); 8B-aligned fills
#define STRD  132               // dist row stride

// smem offsets (floats)
#define OFF_XI  0                        // 128*66 = 8448
#define OFF_XJ  8448                     // 8448
#define OFF_D   16896                    // 128*132 = 16896
#define OFF_SQI 33792                    // 128
#define OFF_SQJ 33920                    // 128
#define SMEM_FLOATS 34048
#define SMEM_DYN (SMEM_FLOATS * 4)       // 136192 bytes

// Scratch (device globals; no dynamic allocation allowed)
__device__ float g_sq[N_PTS];
__device__ float g_pd[(long)NBLK * N_PTS * K_NN];   // partial top-k dists [slot][q][16]
__device__ int   g_pi[(long)NBLK * N_PTS * K_NN];   // partial top-k idx
__device__ int   g_knn[N_PTS * K_NN];
__device__ float g_A[N_PTS * 256];                  // x@(W1-W2)+b
__device__ float g_B[N_PTS * 256];                  // x@W2

// ---------------- helpers ----------------
static __device__ __forceinline__ void ffma2(unsigned long long& acc,
                                             unsigned long long a,
                                             unsigned long long b) {
    asm("fma.rn.f32x2 %0, %1, %2, %0;" : "+l"(acc) : "l"(a), "l"(b));
}
static __device__ __forceinline__ float sum2(unsigned long long p) {
    float lo = __uint_as_float((uint32_t)p);
    float hi = __uint_as_float((uint32_t)(p >> 32));
    return lo + hi;
}
// lexicographic (d, idx) insertion — matches jax top_k tie-breaking
static __device__ __forceinline__ void ins_lex(float d, int i,
                                               float (&kd)[K_NN], int (&ki)[K_NN]) {
    kd[K_NN - 1] = d; ki[K_NN - 1] = i;
#pragma unroll
    for (int t = K_NN - 1; t > 0; --t) {
        bool sw = (kd[t] < kd[t - 1]) ||
                  (kd[t] == kd[t - 1] && ki[t] < ki[t - 1]);
        if (sw) {
            float td = kd[t]; kd[t] = kd[t - 1]; kd[t - 1] = td;
            int ti = ki[t]; ki[t] = ki[t - 1]; ki[t - 1] = ti;
        }
    }
}

// ---------------- 1) squared norms ----------------
__global__ void sqnorm_kernel(const float* __restrict__ x) {
    int i = blockIdx.x * blockDim.x + threadIdx.x;
    const float4* xr = (const float4*)(x + (long)i * C_DIM);
    float s = 0.f;
#pragma unroll
    for (int t = 0; t < C_DIM / 4; ++t) {
        float4 v = xr[t];
        s += v.x * v.x + v.y * v.y + v.z * v.z + v.w * v.w;
    }
    g_sq[i] = s;
}

// ---------------- 2) feature GEMMs: A = x@(W1-W2)+b, B = x@W2 ----------------
__global__ void feat_gemm_kernel(const float* __restrict__ x,
                                 const float* __restrict__ W,
                                 const float* __restrict__ b) {
    __shared__ float xs[16][C_DIM];
    int col = threadIdx.x;
    int row0 = blockIdx.x * 16;
    ((float4*)xs)[col] = ((const float4*)(x + (long)row0 * C_DIM))[col];
    __syncthreads();

    float p1[16], p2[16];
#pragma unroll
    for (int r = 0; r < 16; ++r) { p1[r] = 0.f; p2[r] = 0.f; }
#pragma unroll 4
    for (int c = 0; c < C_DIM; ++c) {
        float w1 = __ldg(W + c * 256 + col);
        float w2 = __ldg(W + (C_DIM + c) * 256 + col);
#pragma unroll
        for (int r = 0; r < 16; ++r) {
            float xv = xs[r][c];
            p1[r] = fmaf(xv, w1, p1[r]);
            p2[r] = fmaf(xv, w2, p2[r]);
        }
    }
    float bias = __ldg(b + col);
#pragma unroll
    for (int r = 0; r < 16; ++r) {
        g_A[(long)(row0 + r) * 256 + col] = p1[r] - p2[r] + bias;
        g_B[(long)(row0 + r) * 256 + col] = p2[r];
    }
}

// ---------------- 3) symmetric block-pair distances + dual-side top-16 ----------------
__global__ void __launch_bounds__(NT) knn_pair_kernel(const float* __restrict__ x) {
    // triangular decode: t = J*(J+1)/2 + I, I <= J
    int t = blockIdx.x;
    int J = (int)((sqrtf(8.f * (float)t + 1.f) - 1.f) * 0.5f);
    while ((J + 1) * (J + 2) / 2 <= t) ++J;
    while (J * (J + 1) / 2 > t) --J;
    int I = t - J * (J + 1) / 2;

    extern __shared__ float sm[];
    int tid = threadIdx.x;
    int i = tid & 127;                  // local row / local query index
    int quarter = tid >> 7;             // j quarter (0..3)
    int qbI = I * BQ, qbJ = J * BQ;

    // ---- fill XI (prescaled by -2; exact), XJ (raw), norms ----
    // stride-66 rows: odd rows only 8B-aligned -> float2 stores
#pragma unroll
    for (int it = 0; it < 4; ++it) {
        int idx = it * NT + tid;        // 2048 float4 per tile
        int r = idx >> 4, cg = idx & 15;
        float4 v = ((const float4*)(x + (long)(qbI + r) * C_DIM))[cg];
        v.x *= -2.f; v.y *= -2.f; v.z *= -2.f; v.w *= -2.f;
        *(float2*)&sm[OFF_XI + r * STRX + cg * 4]     = make_float2(v.x, v.y);
        *(float2*)&sm[OFF_XI + r * STRX + cg * 4 + 2] = make_float2(v.z, v.w);
        float4 w = ((const float4*)(x + (long)(qbJ + r) * C_DIM))[cg];
        *(float2*)&sm[OFF_XJ + r * STRX + cg * 4]     = make_float2(w.x, w.y);
        *(float2*)&sm[OFF_XJ + r * STRX + cg * 4 + 2] = make_float2(w.z, w.w);
    }
    if (tid < BQ) {
        sm[OFF_SQI + tid] = g_sq[qbI + tid];
        sm[OFF_SQJ + tid] = g_sq[qbJ + tid];
    }
    __syncthreads();

    // ---- compute D[i][j] = (-2 x_i) . x_j ; thread = (row i, 32-col quarter) ----
    {
        unsigned long long qr[32];
        const unsigned long long* XIu = (const unsigned long long*)&sm[OFF_XI];
        const unsigned long long* XJu = (const unsigned long long*)&sm[OFF_XJ];
#pragma unroll
        for (int k = 0; k < 32; ++k) qr[k] = XIu[i * 33 + k];
        int j0 = quarter * 32;
#pragma unroll 2
        for (int jj = 0; jj < 32; ++jj) {
            int j = j0 + jj;
            const unsigned long long* bj = XJu + j * 33;   // uniform -> broadcast
            unsigned long long a0 = 0ull, a1 = 0ull;
#pragma unroll
            for (int k = 0; k < 16; ++k) {
                ffma2(a0, qr[2 * k], bj[2 * k]);
                ffma2(a1, qr[2 * k + 1], bj[2 * k + 1]);
            }
            sm[OFF_D + i * STRD + j] = sum2(a0) + sum2(a1);
        }
    }
    __syncthreads();

    // ---- dual scans: warps 0-3 = I-side rows, warps 4-7 = J-side cols ----
    float kd[K_NN];
    int   ki[K_NN];
#pragma unroll
    for (int tt = 0; tt < K_NN; ++tt) { kd[tt] = CUDART_INF_F; ki[tt] = 0x7fffffff; }
    float thr = CUDART_INF_F;
    int   thi = 0x7fffffff;

    if (tid < 128) {
        // I-side: query q = qbI + i, candidates qbJ + j (row float4 reads)
        int q = qbI + i;
        const float* row = &sm[OFF_D + i * STRD];
        const float* sqj = &sm[OFF_SQJ];
#pragma unroll 4
        for (int jb = 0; jb < BQ / 4; ++jb) {
            float4 dv = *(const float4*)(row + jb * 4);
            float4 s4 = *(const float4*)(sqj + jb * 4);
            dv.x += s4.x; dv.y += s4.y; dv.z += s4.z; dv.w += s4.w;
            float mn = fminf(fminf(dv.x, dv.y), fminf(dv.z, dv.w));
            if (mn <= thr) {
                float ds[4] = {dv.x, dv.y, dv.z, dv.w};
#pragma unroll
                for (int e = 0; e < 4; ++e) {
                    int col = qbJ + jb * 4 + e;
                    if (col != q && (ds[e] < thr || (ds[e] == thr && col < thi))) {
                        ins_lex(ds[e], col, kd, ki);
                        thr = kd[K_NN - 1]; thi = ki[K_NN - 1];
                    }
                }
            }
        }
        long base = ((long)J * N_PTS + q) * K_NN;       // slot = J
#pragma unroll
        for (int e = 0; e < K_NN; ++e) { g_pd[base + e] = kd[e]; g_pi[base + e] = ki[e]; }
    } else if (tid < 256 && I != J) {
        // J-side: query q = qbJ + i2, candidates qbI + r (column reads, lane-consecutive)
        int i2 = tid - 128;
        int q = qbJ + i2;
#pragma unroll 4
        for (int rb = 0; rb < BQ / 4; ++rb) {
            float d0 = sm[OFF_D + (rb * 4 + 0) * STRD + i2] + sm[OFF_SQI + rb * 4 + 0];
            float d1 = sm[OFF_D + (rb * 4 + 1) * STRD + i2] + sm[OFF_SQI + rb * 4 + 1];
            float d2 = sm[OFF_D + (rb * 4 + 2) * STRD + i2] + sm[OFF_SQI + rb * 4 + 2];
            float d3 = sm[OFF_D + (rb * 4 + 3) * STRD + i2] + sm[OFF_SQI + rb * 4 + 3];
            float mn = fminf(fminf(d0, d1), fminf(d2, d3));
            if (mn <= thr) {
                float ds[4] = {d0, d1, d2, d3};
#pragma unroll
                for (int e = 0; e < 4; ++e) {
                    int col = qbI + rb * 4 + e;   // I != J -> col != q always
                    if (ds[e] < thr || (ds[e] == thr && col < thi)) {
                        ins_lex(ds[e], col, kd, ki);
                        thr = kd[K_NN - 1]; thi = ki[K_NN - 1];
                    }
                }
            }
        }
        long base = ((long)I * N_PTS + q) * K_NN;       // slot = I
#pragma unroll
        for (int e = 0; e < K_NN; ++e) { g_pd[base + e] = kd[e]; g_pi[base + e] = ki[e]; }
    }
}

// ---------------- 4) merge 128 sorted partial lists per query (float4 groups) ----------------
__global__ void merge_kernel() {
    int q = blockIdx.x * blockDim.x + threadIdx.x;
    float kd[K_NN];
    int   ki[K_NN];
#pragma unroll
    for (int t = 0; t < K_NN; ++t) { kd[t] = CUDART_INF_F; ki[t] = 0x7fffffff; }
    float thr = CUDART_INF_F;
    int   thi = 0x7fffffff;
    for (int s = 0; s < NBLK; ++s) {     // ascending slot = ascending candidate idx
        long base = ((long)s * N_PTS + q) * K_NN;
        const float4* pd4 = (const float4*)(g_pd + base);
        const int4*   pi4 = (const int4*)(g_pi + base);
        bool cont = true;
#pragma unroll 1
        for (int g = 0; g < K_NN / 4 && cont; ++g) {
            float4 d4 = pd4[g];
            int4   c4 = pi4[g];
            float dd[4] = {d4.x, d4.y, d4.z, d4.w};
            int   cc[4] = {c4.x, c4.y, c4.z, c4.w};
#pragma unroll
            for (int e = 0; e < 4; ++e) {
                if (cont) {
                    if (dd[e] < thr || (dd[e] == thr && cc[e] < thi)) {
                        ins_lex(dd[e], cc[e], kd, ki);
                        thr = kd[K_NN - 1]; thi = ki[K_NN - 1];
                    } else {
                        cont = false;    // slot lex-sorted -> rest worse
                    }
                }
            }
        }
    }
#pragma unroll
    for (int t = 0; t < K_NN; ++t) g_knn[(long)q * K_NN + t] = ki[t];
}

// ---------------- 5) gather + max + relu + pixel-shuffle scatter ----------------
__global__ void gather_max_kernel(float* __restrict__ y) {
    int t = threadIdx.x;
    int q = blockIdx.x * 4 + (t >> 6);
    int c = t & 63;
    const int* idx = g_knn + (long)q * K_NN;
    const float4* Bv = (const float4*)g_B;
    float4 m = make_float4(-CUDART_INF_F, -CUDART_INF_F, -CUDART_INF_F, -CUDART_INF_F);
#pragma unroll
    for (int k = 0; k < K_NN; ++k) {
        int j = __ldg(idx + k);
        float4 bv = Bv[(long)j * 64 + c];
        m.x = fmaxf(m.x, bv.x); m.y = fmaxf(m.y, bv.y);
        m.z = fmaxf(m.z, bv.z); m.w = fmaxf(m.w, bv.w);
    }
    float4 a = ((const float4*)g_A)[(long)q * 64 + c];
    y[((long)q * 4 + 0) * 64 + c] = fmaxf(a.x + m.x, 0.f);
    y[((long)q * 4 + 1) * 64 + c] = fmaxf(a.y + m.y, 0.f);
    y[((long)q * 4 + 2) * 64 + c] = fmaxf(a.z + m.z, 0.f);
    y[((long)q * 4 + 3) * 64 + c] = fmaxf(a.w + m.w, 0.f);
}

extern "C" void kernel_launch(void* const* d_in, const int* in_sizes, int n_in,
                              void* d_out, int out_size) {
    const float* x = (const float*)d_in[0];   // (16384, 64) f32
    const float* W = (const float*)d_in[1];   // (128, 256) f32
    const float* b = (const float*)d_in[2];   // (256,) f32
    float* y = (float*)d_out;                 // (65536, 64) f32

    cudaFuncSetAttribute(knn_pair_kernel,
                         cudaFuncAttributeMaxDynamicSharedMemorySize, SMEM_DYN);

    sqnorm_kernel<<<N_PTS / 256, 256>>>(x);
    feat_gemm_kernel<<<N_PTS / 16, 256>>>(x, W, b);
    knn_pair_kernel<<<NPAIR, NT, SMEM_DYN>>>(x);
    merge_kernel<<<N_PTS / 256, 256>>>();
    gather_max_kernel<<<N_PTS / 4, 256>>>(y);
}

// round 16
// speedup vs baseline: 5.7778x; 5.7778x over previous
#include <cuda_runtime.h>
#include <math_constants.h>

#define N_PTS 16384
#define C_DIM 64
#define K_NN  16
#define NSPLIT 8
#define SLICE (N_PTS / NSPLIT)   // 2048
#define BQ 128                    // queries per block (1 per thread)
#define TN 128                    // db points per smem tile

// Scratch (device globals; no dynamic allocation allowed)
__device__ float g_sq[N_PTS];
__device__ float g_pd[NSPLIT * N_PTS * K_NN];   // partial top-k distances
__device__ int   g_pi[NSPLIT * N_PTS * K_NN];   // partial top-k indices
__device__ int   g_knn[N_PTS * K_NN];           // final knn indices
__device__ float g_A[N_PTS * 256];              // x@(W1-W2)+b
__device__ float g_B[N_PTS * 256];              // x@W2

// ---------------- packed f32x2 helpers ----------------
__device__ __forceinline__ unsigned long long ffma2(unsigned long long a,
                                                    unsigned long long b,
                                                    unsigned long long c) {
    unsigned long long d;
    asm("fma.rn.f32x2 %0, %1, %2, %3;" : "=l"(d) : "l"(a), "l"(b), "l"(c));
    return d;
}
__device__ __forceinline__ unsigned long long pack2(float lo, float hi) {
    unsigned long long p;
    asm("mov.b64 %0, {%1, %2};" : "=l"(p) : "f"(lo), "f"(hi));
    return p;
}
__device__ __forceinline__ float sum2(unsigned long long p) {
    float lo, hi;
    asm("mov.b64 {%0, %1}, %2;" : "=f"(lo), "=f"(hi) : "l"(p));
    return lo + hi;
}

// ---------------- 1) squared norms ----------------
__global__ void sqnorm_kernel(const float* __restrict__ x) {
    int i = blockIdx.x * blockDim.x + threadIdx.x;
    const float4* xr = (const float4*)(x + (long)i * C_DIM);
    float s = 0.f;
#pragma unroll
    for (int t = 0; t < C_DIM / 4; ++t) {
        float4 v = xr[t];
        s += v.x * v.x + v.y * v.y + v.z * v.z + v.w * v.w;
    }
    g_sq[i] = s;
}

// ---------------- 2) feature GEMMs: A = x@(W1-W2)+b, B = x@W2 ----------------
__global__ void feat_gemm_kernel(const float* __restrict__ x,
                                 const float* __restrict__ W,
                                 const float* __restrict__ b) {
    __shared__ float xs[16][C_DIM];
    int col = threadIdx.x;             // 0..255  (output column)
    int row0 = blockIdx.x * 16;
    ((float4*)xs)[col] = ((const float4*)(x + (long)row0 * C_DIM))[col];
    __syncthreads();

    float p1[16], p2[16];
#pragma unroll
    for (int r = 0; r < 16; ++r) { p1[r] = 0.f; p2[r] = 0.f; }

#pragma unroll 4
    for (int c = 0; c < C_DIM; ++c) {
        float w1 = __ldg(W + c * 256 + col);
        float w2 = __ldg(W + (C_DIM + c) * 256 + col);
#pragma unroll
        for (int r = 0; r < 16; ++r) {
            float xv = xs[r][c];       // broadcast LDS (uniform across warp)
            p1[r] = fmaf(xv, w1, p1[r]);
            p2[r] = fmaf(xv, w2, p2[r]);
        }
    }
    float bias = __ldg(b + col);
#pragma unroll
    for (int r = 0; r < 16; ++r) {
        g_A[(long)(row0 + r) * 256 + col] = p1[r] - p2[r] + bias;
        g_B[(long)(row0 + r) * 256 + col] = p2[r];
    }
}

// ---------------- 3) KNN (split-K over db), f32x2, DUAL acc chains ----------------
__global__ __launch_bounds__(BQ, 4) void knn_part_kernel(const float* __restrict__ x) {
    __shared__ float db_s[TN * C_DIM];
    __shared__ float sq_s[TN];
    int tid = threadIdx.x;
    int q = blockIdx.x * BQ + tid;
    int s0 = blockIdx.y * SLICE;

    // query row in registers as 32 packed f32x2
    unsigned long long q2[C_DIM / 2];
    {
        const float2* xr = (const float2*)(x + (long)q * C_DIM);
#pragma unroll
        for (int t = 0; t < C_DIM / 2; ++t) {
            float2 v = xr[t];
            q2[t] = pack2(v.x, v.y);
        }
    }
    float sqq = g_sq[q];

    float kd[K_NN];
    int   ki[K_NN];
#pragma unroll
    for (int t = 0; t < K_NN; ++t) { kd[t] = CUDART_INF_F; ki[t] = -1; }

    for (int tile = 0; tile < SLICE / TN; ++tile) {
        int base = s0 + tile * TN;
        __syncthreads();
#pragma unroll
        for (int it = 0; it < (TN * C_DIM / 4) / BQ; ++it) {
            int off = it * BQ + tid;
            ((float4*)db_s)[off] = ((const float4*)(x + (long)base * C_DIM))[off];
        }
        sq_s[tid] = g_sq[base + tid];
        __syncthreads();

        for (int j = 0; j < TN; ++j) {
            const unsigned long long* db2 =
                (const unsigned long long*)(db_s + j * C_DIM);
            unsigned long long a0 = 0ull, a1 = 0ull;   // two chains: dep spacing 2
#pragma unroll
            for (int cc = 0; cc < C_DIM / 4; ++cc) {
                a0 = ffma2(q2[2 * cc], db2[2 * cc], a0);
                a1 = ffma2(q2[2 * cc + 1], db2[2 * cc + 1], a1);
            }
            float dot = sum2(a0) + sum2(a1);
            float d = sqq + sq_s[j] - 2.f * dot;
            int col = base + j;
            if (d < kd[K_NN - 1] && col != q) {
                kd[K_NN - 1] = d; ki[K_NN - 1] = col;
#pragma unroll
                for (int t = K_NN - 1; t > 0; --t) {
                    if (kd[t] < kd[t - 1]) {
                        float td = kd[t]; kd[t] = kd[t - 1]; kd[t - 1] = td;
                        int ti = ki[t]; ki[t] = ki[t - 1]; ki[t - 1] = ti;
                    }
                }
            }
        }
    }
    long ob = ((long)blockIdx.y * N_PTS + q) * K_NN;
#pragma unroll
    for (int t = 0; t < K_NN; ++t) { g_pd[ob + t] = kd[t]; g_pi[ob + t] = ki[t]; }
}

// ---------------- 4) merge split-K partial top-k lists ----------------
__global__ void merge_kernel() {
    int q = blockIdx.x * blockDim.x + threadIdx.x;
    float kd[K_NN];
    int   ki[K_NN];
#pragma unroll
    for (int t = 0; t < K_NN; ++t) { kd[t] = CUDART_INF_F; ki[t] = -1; }
    // candidates visited in ascending global index order -> jax tie-break match
    for (int s = 0; s < NSPLIT; ++s) {
        long ob = ((long)s * N_PTS + q) * K_NN;
#pragma unroll
        for (int t2 = 0; t2 < K_NN; ++t2) {
            float d = g_pd[ob + t2];
            int   i = g_pi[ob + t2];
            if (d < kd[K_NN - 1]) {
                kd[K_NN - 1] = d; ki[K_NN - 1] = i;
#pragma unroll
                for (int t = K_NN - 1; t > 0; --t) {
                    if (kd[t] < kd[t - 1]) {
                        float td = kd[t]; kd[t] = kd[t - 1]; kd[t - 1] = td;
                        int ti = ki[t]; ki[t] = ki[t - 1]; ki[t - 1] = ti;
                    }
                }
            }
        }
    }
#pragma unroll
    for (int t = 0; t < K_NN; ++t) g_knn[(long)q * K_NN + t] = ki[t];
}

// ---------------- 5) gather + max + relu + pixel-shuffle scatter ----------------
__global__ void gather_max_kernel(float* __restrict__ y) {
    int t = threadIdx.x;
    int q = blockIdx.x * 4 + (t >> 6);
    int c = t & 63;
    const int* idx = g_knn + (long)q * K_NN;
    const float4* Bv = (const float4*)g_B;
    float4 m = make_float4(-CUDART_INF_F, -CUDART_INF_F, -CUDART_INF_F, -CUDART_INF_F);
#pragma unroll
    for (int k = 0; k < K_NN; ++k) {
        int j = __ldg(idx + k);
        float4 bv = Bv[(long)j * 64 + c];
        m.x = fmaxf(m.x, bv.x); m.y = fmaxf(m.y, bv.y);
        m.z = fmaxf(m.z, bv.z); m.w = fmaxf(m.w, bv.w);
    }
    float4 a = ((const float4*)g_A)[(long)q * 64 + c];
    y[((long)q * 4 + 0) * 64 + c] = fmaxf(a.x + m.x, 0.f);
    y[((long)q * 4 + 1) * 64 + c] = fmaxf(a.y + m.y, 0.f);
    y[((long)q * 4 + 2) * 64 + c] = fmaxf(a.z + m.z, 0.f);
    y[((long)q * 4 + 3) * 64 + c] = fmaxf(a.w + m.w, 0.f);
}

extern "C" void kernel_launch(void* const* d_in, const int* in_sizes, int n_in,
                              void* d_out, int out_size) {
    const float* x = (const float*)d_in[0];   // (16384, 64) f32
    const float* W = (const float*)d_in[1];   // (128, 256) f32
    const float* b = (const float*)d_in[2];   // (256,) f32
    float* y = (float*)d_out;                 // (65536, 64) f32

    sqnorm_kernel<<<N_PTS / 256, 256>>>(x);
    feat_gemm_kernel<<<N_PTS / 16, 256>>>(x, W, b);
    knn_part_kernel<<<dim3(N_PTS / BQ, NSPLIT), BQ>>>(x);
    merge_kernel<<<N_PTS / 64, 64>>>();
    gather_max_kernel<<<N_PTS / 4, 256>>>(y);
}